// round 4
// baseline (speedup 1.0000x reference)
#include <cuda_runtime.h>
#include <cstddef>

#define NBOX 1024
#define S    32
#define C    64
#define HF   192
#define WF   192
#define IST  244   // per-ic stride in sIn (6 rows * 40 slots + 4 pad; %4==0 for float4, gcd(20,32)=4 -> only 4-way STS conflict on fill)

// Ping-pong scratch (no allocation allowed -> __device__ globals)
__device__ float g_buf0[NBOX * S * S * C];
__device__ float g_buf1[NBOX * S * S * C];

// ---------------- packed fp32x2 helpers (sm_100+ PTX) ----------------
__device__ __forceinline__ unsigned long long bcast2(float x) {
    unsigned long long r;
    unsigned u = __float_as_uint(x);
    asm("mov.b64 %0, {%1, %1};" : "=l"(r) : "r"(u));
    return r;
}
__device__ __forceinline__ void ffma2(unsigned long long& acc,
                                      unsigned long long a,
                                      unsigned long long b) {
    asm("fma.rn.f32x2 %0, %1, %2, %0;" : "+l"(acc) : "l"(a), "l"(b));
}
union U64F2 { unsigned long long u; float2 f; };

// ---------------- Kernel 1: crop_and_resize ----------------
// One block per (box, output row). 256 threads: x = tid>>3 (32), c0 = (tid&7)*8.
__global__ void __launch_bounds__(256) crop_kernel(const float* __restrict__ feat,
                                                   const float* __restrict__ boxes,
                                                   const int* __restrict__ box_ids) {
    int blk = blockIdx.x;
    int box = blk >> 5;
    int y   = blk & 31;
    int tid = threadIdx.x;

    float by1 = boxes[box * 4 + 0];
    float bx1 = boxes[box * 4 + 1];
    float by2 = boxes[box * 4 + 2];
    float bx2 = boxes[box * 4 + 3];
    int   bi  = box_ids[box];

    float ty = (float)y * (1.0f / 31.0f);
    float ys = (by1 + ty * (by2 - by1)) * 191.0f;
    float y0f = fminf(fmaxf(floorf(ys), 0.0f), 191.0f);
    float wy = ys - y0f;
    int y0i = (int)y0f;
    int y1i = min(y0i + 1, 191);

    int x  = tid >> 3;
    int c0 = (tid & 7) * 8;
    float tx = (float)x * (1.0f / 31.0f);
    float xs = (bx1 + tx * (bx2 - bx1)) * 191.0f;
    float x0f = fminf(fmaxf(floorf(xs), 0.0f), 191.0f);
    float wx = xs - x0f;
    int x0i = (int)x0f;
    int x1i = min(x0i + 1, 191);

    const float* fb = feat + (size_t)bi * HF * WF * C;
    const float4* p00 = (const float4*)(fb + ((size_t)y0i * WF + x0i) * C + c0);
    const float4* p01 = (const float4*)(fb + ((size_t)y0i * WF + x1i) * C + c0);
    const float4* p10 = (const float4*)(fb + ((size_t)y1i * WF + x0i) * C + c0);
    const float4* p11 = (const float4*)(fb + ((size_t)y1i * WF + x1i) * C + c0);

    float omwx = 1.0f - wx, omwy = 1.0f - wy;
    float4* o = (float4*)(g_buf0 + ((size_t)(box * S + y) * S + x) * C + c0);

#pragma unroll
    for (int h = 0; h < 2; h++) {
        float4 v00 = p00[h], v01 = p01[h], v10 = p10[h], v11 = p11[h];
        float4 r;
        r.x = (v00.x * omwx + v01.x * wx) * omwy + (v10.x * omwx + v11.x * wx) * wy;
        r.y = (v00.y * omwx + v01.y * wx) * omwy + (v10.y * omwx + v11.y * wx) * wy;
        r.z = (v00.z * omwx + v01.z * wx) * omwy + (v10.z * omwx + v11.z * wx) * wy;
        r.w = (v00.w * omwx + v01.w * wx) * omwy + (v10.w * omwx + v11.w * wx) * wy;
        o[h] = r;
    }
}

// ---------------- Kernel 2: 3x3 SAME conv 64->64 + ReLU ----------------
// Block = (rowtile of 4 rows [blockIdx.x], box [blockIdx.y]). 256 threads.
// Thread: ocg = tid&15 -> oc0=4*ocg ; pg = tid>>4 -> j = pg>>2 (row), x0 = (pg&3)*8.
// smem: sIn[64][IST] transposed (ic-major, rows y0-1..y0+4, x slots 0..39 with x+4 shift,
//       pads zero for SAME padding) + sW[3][64][64] = one ky weight slice.
__global__ void __launch_bounds__(256, 2) conv3_relu_kernel(const float* __restrict__ w,
                                                            const float* __restrict__ bias,
                                                            int dir) {
    extern __shared__ float sm[];
    float* sIn = sm;                 // 64 * IST floats
    float* sW  = sm + 64 * IST;      // 3*64*64 floats

    const float* in  = dir ? g_buf1 : g_buf0;
    float*       out = dir ? g_buf0 : g_buf1;

    int box = blockIdx.y;
    int y0  = blockIdx.x * 4;
    int tid = threadIdx.x;

    // zero the whole transposed tile (covers SAME padding + x-slot pads)
    for (int e = tid; e < 64 * IST; e += 256) sIn[e] = 0.0f;
    __syncthreads();

    // fill valid region: read [gy][x][c] coalesced over c, store transposed
    const float* inb = in + (size_t)box * S * S * C;
    for (int e = tid; e < 64 * 6 * 32; e += 256) {
        int c  = e & 63;
        int xx = (e >> 6) & 31;
        int r  = e >> 11;
        int gy = y0 - 1 + r;
        if ((unsigned)gy < 32u)
            sIn[c * IST + r * 40 + 4 + xx] = inb[((size_t)(gy * 32 + xx)) * C + c];
    }

    int ocg = tid & 15, pg = tid >> 4;
    int oc0 = ocg * 4;
    int j   = pg >> 2;        // output row within tile
    int x0  = (pg & 3) * 8;   // first of 8 consecutive x

    unsigned long long acc[8][2];
#pragma unroll
    for (int p = 0; p < 8; p++) { acc[p][0] = 0ull; acc[p][1] = 0ull; }

    for (int ky = 0; ky < 3; ky++) {
        __syncthreads();
        // stage weight slice for this ky (contiguous 12288 floats)
        for (int e = tid; e < 3 * 64 * 64; e += 256) sW[e] = w[ky * (3 * 64 * 64) + e];
        __syncthreads();

        const float* rowp = sIn + (j + ky) * 40 + x0;  // slot x0 == input x (x0-4)
#pragma unroll 2
        for (int ic = 0; ic < 64; ic++) {
            const float4* a4 = (const float4*)(rowp + ic * IST);
            float4 A0 = a4[0], A1 = a4[1], A2 = a4[2], A3 = a4[3];
            // window covers input x in [x0-4, x0+12); needed: x0-1..x0+8 -> idx 3..12
            unsigned long long pv[10];
            pv[0] = bcast2(A0.w);
            pv[1] = bcast2(A1.x); pv[2] = bcast2(A1.y); pv[3] = bcast2(A1.z); pv[4] = bcast2(A1.w);
            pv[5] = bcast2(A2.x); pv[6] = bcast2(A2.y); pv[7] = bcast2(A2.z); pv[8] = bcast2(A2.w);
            pv[9] = bcast2(A3.x);
#pragma unroll
            for (int kx = 0; kx < 3; kx++) {
                ulonglong2 wk = *(const ulonglong2*)(sW + (kx * 64 + ic) * 64 + oc0);
#pragma unroll
                for (int p = 0; p < 8; p++) {
                    ffma2(acc[p][0], pv[p + kx], wk.x);
                    ffma2(acc[p][1], pv[p + kx], wk.y);
                }
            }
        }
    }

    float b0 = bias[oc0], b1 = bias[oc0 + 1], b2 = bias[oc0 + 2], b3 = bias[oc0 + 3];
    float* ob = out + (((size_t)box * S + (y0 + j)) * S + x0) * C + oc0;
#pragma unroll
    for (int p = 0; p < 8; p++) {
        U64F2 lo, hi;
        lo.u = acc[p][0];
        hi.u = acc[p][1];
        float4 v;
        v.x = fmaxf(lo.f.x + b0, 0.0f);
        v.y = fmaxf(lo.f.y + b1, 0.0f);
        v.z = fmaxf(hi.f.x + b2, 0.0f);
        v.w = fmaxf(hi.f.y + b3, 0.0f);
        *(float4*)(ob + (size_t)p * C) = v;
    }
}

// ---------------- Kernel 3: 3x3 VALID conv 64->3, only the selected class ----------------
__global__ void __launch_bounds__(256) outconv_kernel(const float* __restrict__ ow,
                                                      const float* __restrict__ obias,
                                                      const int* __restrict__ cls,
                                                      float* __restrict__ out) {
    __shared__ float sW[576];
    int box = blockIdx.x;
    int cl  = cls[box];
    int tid = threadIdx.x;
    for (int e = tid; e < 576; e += 256) sW[e] = ow[e * 3 + cl];
    __syncthreads();
    float bb = obias[cl];
    const float* inb = g_buf0 + (size_t)box * S * S * C;

    for (int p = tid; p < 900; p += 256) {
        int oy = p / 30;
        int ox = p - oy * 30;
        float acc = 0.0f;
        for (int ky = 0; ky < 3; ky++) {
            for (int kx = 0; kx < 3; kx++) {
                const float4* iv = (const float4*)(inb + ((size_t)((oy + ky) * 32 + (ox + kx))) * C);
                const float4* wv = (const float4*)(sW + (ky * 3 + kx) * 64);
#pragma unroll
                for (int q = 0; q < 16; q++) {
                    float4 a = iv[q], b = wv[q];
                    acc += a.x * b.x + a.y * b.y + a.z * b.z + a.w * b.w;
                }
            }
        }
        out[(size_t)box * 900 + p] = acc + bb;
    }
}

// ---------------- launch ----------------
extern "C" void kernel_launch(void* const* d_in, const int* in_sizes, int n_in,
                              void* d_out, int out_size) {
    const float* features = (const float*)d_in[0];
    const float* boxes    = (const float*)d_in[1];
    const int*   box_ids  = (const int*)d_in[2];
    const int*   cls      = (const int*)d_in[3];
    const float* c1w      = (const float*)d_in[4];
    const float* c1b      = (const float*)d_in[5];
    const float* c2w      = (const float*)d_in[6];
    const float* c2b      = (const float*)d_in[7];
    const float* ow       = (const float*)d_in[8];
    const float* obias    = (const float*)d_in[9];
    float* out = (float*)d_out;

    const int conv_smem = (64 * IST + 3 * 64 * 64) * (int)sizeof(float);  // 111616 B
    cudaFuncSetAttribute(conv3_relu_kernel,
                         cudaFuncAttributeMaxDynamicSharedMemorySize, conv_smem);

    crop_kernel<<<NBOX * S, 256>>>(features, boxes, box_ids);
    conv3_relu_kernel<<<dim3(8, NBOX), 256, conv_smem>>>(c1w, c1b, 0);  // buf0 -> buf1
    conv3_relu_kernel<<<dim3(8, NBOX), 256, conv_smem>>>(c2w, c2b, 1);  // buf1 -> buf0
    outconv_kernel<<<NBOX, 256>>>(ow, obias, cls, out);
}

// round 6
// speedup vs baseline: 5.2018x; 5.2018x over previous
#include <cuda_runtime.h>
#include <cuda_fp16.h>
#include <cstdint>
#include <cstddef>

#define NBOX 1024
#define S    32
#define C    64
#define HF   192
#define WF   192

// ---------------- device scratch (no allocation allowed) ----------------
__device__ __half g_h0[NBOX * S * S * C];   // crop out / conv1 in (half)
__device__ __half g_h1[NBOX * S * S * C];   // conv1 out / conv2 in (half)
__device__ float  g_buf0[NBOX * S * S * C]; // conv2 out (float) for outconv
// pre-transposed, pre-swizzled half weights: [conv][9 taps][64 ic][64 oc]
__device__ __half g_wh[2 * 9 * 64 * 64];

// ---------------- helpers ----------------
__device__ __forceinline__ uint32_t smem_u32(const void* p) {
    uint32_t a;
    asm("{ .reg .u64 t; cvta.to.shared.u64 t, %1; cvt.u32.u64 %0, t; }" : "=r"(a) : "l"(p));
    return a;
}
__device__ __forceinline__ void ldmatrix_x4(uint32_t* r, uint32_t addr) {
    asm volatile("ldmatrix.sync.aligned.m8n8.x4.shared.b16 {%0,%1,%2,%3}, [%4];"
                 : "=r"(r[0]), "=r"(r[1]), "=r"(r[2]), "=r"(r[3]) : "r"(addr));
}
__device__ __forceinline__ void ldmatrix_x2t(uint32_t& b0, uint32_t& b1, uint32_t addr) {
    asm volatile("ldmatrix.sync.aligned.m8n8.x2.trans.shared.b16 {%0,%1}, [%2];"
                 : "=r"(b0), "=r"(b1) : "r"(addr));
}
__device__ __forceinline__ void mma16816(float* d, const uint32_t* a, uint32_t b0, uint32_t b1) {
    asm volatile(
        "mma.sync.aligned.m16n8k16.row.col.f32.f16.f16.f32 "
        "{%0,%1,%2,%3}, {%4,%5,%6,%7}, {%8,%9}, {%0,%1,%2,%3};"
        : "+f"(d[0]), "+f"(d[1]), "+f"(d[2]), "+f"(d[3])
        : "r"(a[0]), "r"(a[1]), "r"(a[2]), "r"(a[3]), "r"(b0), "r"(b1));
}

// ---------------- Kernel 0: weight prep (transpose + half + swizzle) ----------------
// src [ky][kx][ic][oc] f32 -> g_wh[conv][tap][ic][(oc-chunk ^ (ic&7))*8 + oc%8] half
__global__ void __launch_bounds__(256) wprep_kernel(const float* __restrict__ c1w,
                                                    const float* __restrict__ c2w) {
    int b = blockIdx.x;            // 0..17
    int cw = b / 9, kk = b % 9;
    const float* src = (cw ? c2w : c1w) + kk * 4096;   // [ic][oc] slice
    char* dst = (char*)(g_wh + b * 4096);
#pragma unroll
    for (int i = 0; i < 16; i++) {
        int e = i * 256 + threadIdx.x;   // e = ic*64 + oc
        int ic = e >> 6, oc = e & 63;
        __half v = __float2half_rn(src[e]);
        int boff = ic * 128 + (((oc >> 3) ^ (ic & 7)) << 4) + (oc & 7) * 2;
        *(__half*)(dst + boff) = v;
    }
}

// ---------------- Kernel 1: crop_and_resize -> half ----------------
__global__ void __launch_bounds__(256) crop_kernel(const float* __restrict__ feat,
                                                   const float* __restrict__ boxes,
                                                   const int* __restrict__ box_ids) {
    int blk = blockIdx.x;
    int box = blk >> 5;
    int y   = blk & 31;
    int tid = threadIdx.x;

    float by1 = boxes[box * 4 + 0];
    float bx1 = boxes[box * 4 + 1];
    float by2 = boxes[box * 4 + 2];
    float bx2 = boxes[box * 4 + 3];
    int   bi  = box_ids[box];

    float ty = (float)y * (1.0f / 31.0f);
    float ys = (by1 + ty * (by2 - by1)) * 191.0f;
    float y0f = fminf(fmaxf(floorf(ys), 0.0f), 191.0f);
    float wy = ys - y0f;
    int y0i = (int)y0f;
    int y1i = min(y0i + 1, 191);

    int x  = tid >> 3;
    int c0 = (tid & 7) * 8;
    float tx = (float)x * (1.0f / 31.0f);
    float xs = (bx1 + tx * (bx2 - bx1)) * 191.0f;
    float x0f = fminf(fmaxf(floorf(xs), 0.0f), 191.0f);
    float wx = xs - x0f;
    int x0i = (int)x0f;
    int x1i = min(x0i + 1, 191);

    const float* fb = feat + (size_t)bi * HF * WF * C;
    const float4* p00 = (const float4*)(fb + ((size_t)y0i * WF + x0i) * C + c0);
    const float4* p01 = (const float4*)(fb + ((size_t)y0i * WF + x1i) * C + c0);
    const float4* p10 = (const float4*)(fb + ((size_t)y1i * WF + x0i) * C + c0);
    const float4* p11 = (const float4*)(fb + ((size_t)y1i * WF + x1i) * C + c0);

    float omwx = 1.0f - wx, omwy = 1.0f - wy;
    __half2 hh[4];
#pragma unroll
    for (int h = 0; h < 2; h++) {
        float4 v00 = p00[h], v01 = p01[h], v10 = p10[h], v11 = p11[h];
        float4 r;
        r.x = (v00.x * omwx + v01.x * wx) * omwy + (v10.x * omwx + v11.x * wx) * wy;
        r.y = (v00.y * omwx + v01.y * wx) * omwy + (v10.y * omwx + v11.y * wx) * wy;
        r.z = (v00.z * omwx + v01.z * wx) * omwy + (v10.z * omwx + v11.z * wx) * wy;
        r.w = (v00.w * omwx + v01.w * wx) * omwy + (v10.w * omwx + v11.w * wx) * wy;
        hh[h * 2 + 0] = __floats2half2_rn(r.x, r.y);
        hh[h * 2 + 1] = __floats2half2_rn(r.z, r.w);
    }
    __half* o = g_h0 + ((size_t)(box * S + y) * S + x) * C + c0;
    *(uint4*)o = *(uint4*)hh;
}

// ---------------- Kernel 2: 3x3 SAME conv 64->64 + ReLU via mma.sync f16 ----------------
// grid (8, NBOX): blockIdx.x = 4-row tile, blockIdx.y = box. 256 threads = 8 warps.
// SMEM: sIn halo [6 rows][34 x][64 ic] half, 16B-chunk swizzled (26112 B) @0
//       sW  9 taps x [64 ic][64 oc] half, pre-swizzled (73728 B)          @26112
// Warp w: m-tile = (w&3)*32 (32 pixels), n-tile = (w>>2)*32 (32 oc).
#define OFF_W     26112
#define CONV_SMEM (26112 + 73728)

template <int DOCVT>
__global__ void __launch_bounds__(256, 2) conv_mma_kernel(const __half* __restrict__ in,
                                                          __half* __restrict__ outh,
                                                          float* __restrict__ outf,
                                                          const __half* __restrict__ wsrc,
                                                          const float* __restrict__ bias) {
    extern __shared__ char sm[];
    uint32_t smb = smem_u32(sm);
    int tid = threadIdx.x;
    int box = blockIdx.y;
    int y0  = blockIdx.x * 4;

    // ---- stage halo tile (6 x 34 x 64 half, zero-padded, chunk-swizzled) ----
    {
        const char* inb = (const char*)(in + (size_t)box * 65536);
#pragma unroll
        for (int i = 0; i < 7; i++) {
            int q = i * 256 + tid;           // 16B chunk id, 0..1631
            if (q < 1632) {
                int p = q >> 3, c = q & 7;   // pixel in tile, chunk
                int r = p / 34, xs = p - r * 34;
                int gy = y0 - 1 + r, gx = xs - 1;
                uint4 v = make_uint4(0u, 0u, 0u, 0u);
                if ((unsigned)gy < 32u && (unsigned)gx < 32u)
                    v = *(const uint4*)(inb + ((size_t)(gy * 32 + gx)) * 128 + c * 16);
                *(uint4*)(sm + p * 128 + ((c ^ (p & 7)) << 4)) = v;
            }
        }
    }
    // ---- stage weights (linear copy of pre-swizzled image) ----
    {
        const uint4* src = (const uint4*)wsrc;
        uint4* dst = (uint4*)(sm + OFF_W);
#pragma unroll
        for (int i = 0; i < 18; i++) dst[i * 256 + tid] = src[i * 256 + tid];
    }
    __syncthreads();

    int lane = tid & 31, w = tid >> 5;
    int mt0 = (w & 3) * 32;
    int n0  = (w >> 2) * 32;
    int lr  = lane & 15;
    int khalf = lane >> 4;

    int jA[2], xA[2];
#pragma unroll
    for (int mi = 0; mi < 2; mi++) {
        int m = mt0 + mi * 16 + lr;
        jA[mi] = m >> 5;
        xA[mi] = m & 31;
    }
    int icl = lane & 15;
    int nc0 = n0 >> 3;

    float acc[2][4][4];
#pragma unroll
    for (int mi = 0; mi < 2; mi++)
#pragma unroll
        for (int ni = 0; ni < 4; ni++)
#pragma unroll
            for (int k = 0; k < 4; k++) acc[mi][ni][k] = 0.0f;

    for (int tap = 0; tap < 9; tap++) {
        int ky = tap / 3, kx = tap - ky * 3;
        uint32_t pixb[2];
        pixb[0] = (jA[0] + ky) * 34 + xA[0] + kx;
        pixb[1] = (jA[1] + ky) * 34 + xA[1] + kx;
        uint32_t swt = smb + OFF_W + tap * 8192;
#pragma unroll
        for (int ks = 0; ks < 4; ks++) {
            uint32_t a[2][4];
            uint32_t kc = ks * 2 + khalf;
#pragma unroll
            for (int mi = 0; mi < 2; mi++) {
                uint32_t ad = smb + pixb[mi] * 128 + (((kc ^ (pixb[mi] & 7)) & 7) << 4);
                ldmatrix_x4(a[mi], ad);
            }
            uint32_t ic = ks * 16 + icl;
            uint32_t rowb = swt + ic * 128;
#pragma unroll
            for (int ni = 0; ni < 4; ni++) {
                uint32_t ch = ((nc0 + ni) ^ (ic & 7)) & 7;
                uint32_t b0, b1;
                ldmatrix_x2t(b0, b1, rowb + (ch << 4));
                mma16816(acc[0][ni], a[0], b0, b1);
                mma16816(acc[1][ni], a[1], b0, b1);
            }
        }
    }

    // ---- epilogue: bias + relu; write half (conv1) or float (conv2) ----
    int rowg = lane >> 2;
    int colg = (lane & 3) * 2;
    size_t obase = (size_t)box * 65536 + (size_t)y0 * 32 * 64;
#pragma unroll
    for (int ni = 0; ni < 4; ni++) {
        int oc = n0 + ni * 8 + colg;
        float bx = __ldg(bias + oc), by = __ldg(bias + oc + 1);
#pragma unroll
        for (int mi = 0; mi < 2; mi++) {
#pragma unroll
            for (int h = 0; h < 2; h++) {
                int m = mt0 + mi * 16 + rowg + h * 8;
                float v0 = fmaxf(acc[mi][ni][h * 2 + 0] + bx, 0.0f);
                float v1 = fmaxf(acc[mi][ni][h * 2 + 1] + by, 0.0f);
                size_t idx = obase + (size_t)m * 64 + oc;
                if (DOCVT) {
                    *(__half2*)(outh + idx) = __floats2half2_rn(v0, v1);
                } else {
                    *(float2*)(outf + idx) = make_float2(v0, v1);
                }
            }
        }
    }
}

// ---------------- Kernel 3: 3x3 VALID conv 64->1 (selected class), channel-split teams ----
__global__ void __launch_bounds__(256) outconv_kernel(const float* __restrict__ ow,
                                                      const float* __restrict__ obias,
                                                      const int* __restrict__ cls,
                                                      float* __restrict__ out) {
    __shared__ float sW[576];
    int box = blockIdx.x;
    int cl  = cls[box];
    int tid = threadIdx.x;
    for (int e = tid; e < 576; e += 256) sW[e] = ow[e * 3 + cl];
    __syncthreads();

    int sub = tid & 7, team = tid >> 3;
    int c0 = sub * 8;
    float4 wv[18];
#pragma unroll
    for (int p9 = 0; p9 < 9; p9++) {
        wv[p9 * 2 + 0] = *(const float4*)(sW + p9 * 64 + c0);
        wv[p9 * 2 + 1] = *(const float4*)(sW + p9 * 64 + c0 + 4);
    }
    float bb = obias[cl];
    const float* inb = g_buf0 + (size_t)box * 65536;

    for (int p = team; p < 900; p += 32) {
        int oy = p / 30;
        int ox = p - oy * 30;
        float acc = 0.0f;
#pragma unroll
        for (int ky = 0; ky < 3; ky++) {
#pragma unroll
            for (int kx = 0; kx < 3; kx++) {
                const float4* iv = (const float4*)(inb + ((size_t)((oy + ky) * 32 + ox + kx)) * 64 + c0);
                float4 a0 = iv[0], a1 = iv[1];
                int wi = (ky * 3 + kx) * 2;
                acc += a0.x * wv[wi].x + a0.y * wv[wi].y + a0.z * wv[wi].z + a0.w * wv[wi].w;
                acc += a1.x * wv[wi + 1].x + a1.y * wv[wi + 1].y + a1.z * wv[wi + 1].z + a1.w * wv[wi + 1].w;
            }
        }
        acc += __shfl_down_sync(0xffffffff, acc, 4, 8);
        acc += __shfl_down_sync(0xffffffff, acc, 2, 8);
        acc += __shfl_down_sync(0xffffffff, acc, 1, 8);
        if (sub == 0) out[(size_t)box * 900 + p] = acc + bb;
    }
}

// ---------------- launch ----------------
extern "C" void kernel_launch(void* const* d_in, const int* in_sizes, int n_in,
                              void* d_out, int out_size) {
    const float* features = (const float*)d_in[0];
    const float* boxes    = (const float*)d_in[1];
    const int*   box_ids  = (const int*)d_in[2];
    const int*   cls      = (const int*)d_in[3];
    const float* c1w      = (const float*)d_in[4];
    const float* c1b      = (const float*)d_in[5];
    const float* c2w      = (const float*)d_in[6];
    const float* c2b      = (const float*)d_in[7];
    const float* ow       = (const float*)d_in[8];
    const float* obias    = (const float*)d_in[9];
    float* out = (float*)d_out;

    static int init_done = 0;
    if (!init_done) {
        cudaFuncSetAttribute(conv_mma_kernel<1>,
                             cudaFuncAttributeMaxDynamicSharedMemorySize, CONV_SMEM);
        cudaFuncSetAttribute(conv_mma_kernel<0>,
                             cudaFuncAttributeMaxDynamicSharedMemorySize, CONV_SMEM);
        init_done = 1;
    }

    __half* wh0;  cudaGetSymbolAddress((void**)&wh0, g_wh);
    __half* h0;   cudaGetSymbolAddress((void**)&h0, g_h0);
    __half* h1;   cudaGetSymbolAddress((void**)&h1, g_h1);
    float*  b0f;  cudaGetSymbolAddress((void**)&b0f, g_buf0);

    wprep_kernel<<<18, 256>>>(c1w, c2w);
    crop_kernel<<<NBOX * S, 256>>>(features, boxes, box_ids);
    conv_mma_kernel<1><<<dim3(8, NBOX), 256, CONV_SMEM>>>(h0, h1, nullptr, wh0, c1b);
    conv_mma_kernel<0><<<dim3(8, NBOX), 256, CONV_SMEM>>>(h1, nullptr, b0f, wh0 + 9 * 4096, c2b);
    outconv_kernel<<<NBOX, 256>>>(ow, obias, cls, out);
}

// round 7
// speedup vs baseline: 5.9794x; 1.1495x over previous
#include <cuda_runtime.h>
#include <cuda_fp16.h>
#include <cstdint>
#include <cstddef>

#define NBOX 1024
#define S    32
#define C    64
#define HF   192
#define WF   192

// ---------------- device scratch (no allocation allowed) ----------------
__device__ __half g_h0[NBOX * S * S * C];   // crop out / conv1 in ; conv2 out
__device__ __half g_h1[NBOX * S * S * C];   // conv1 out / conv2 in
// fragment-ordered half weights: [conv][tap][ks][ni][lane] -> uint2 (4 halves)
__device__ __half g_wfrag[2 * 9 * 4 * 8 * 32 * 4];

// ---------------- helpers ----------------
__device__ __forceinline__ uint32_t smem_u32(const void* p) {
    uint32_t a;
    asm("{ .reg .u64 t; cvta.to.shared.u64 t, %1; cvt.u32.u64 %0, t; }" : "=r"(a) : "l"(p));
    return a;
}
__device__ __forceinline__ void ldmatrix_x4(uint32_t* r, uint32_t addr) {
    asm volatile("ldmatrix.sync.aligned.m8n8.x4.shared.b16 {%0,%1,%2,%3}, [%4];"
                 : "=r"(r[0]), "=r"(r[1]), "=r"(r[2]), "=r"(r[3]) : "r"(addr));
}
__device__ __forceinline__ void mma16816(float* d, const uint32_t* a, uint32_t b0, uint32_t b1) {
    asm volatile(
        "mma.sync.aligned.m16n8k16.row.col.f32.f16.f16.f32 "
        "{%0,%1,%2,%3}, {%4,%5,%6,%7}, {%8,%9}, {%0,%1,%2,%3};"
        : "+f"(d[0]), "+f"(d[1]), "+f"(d[2]), "+f"(d[3])
        : "r"(a[0]), "r"(a[1]), "r"(a[2]), "r"(a[3]), "r"(b0), "r"(b1));
}

// ---------------- Kernel 0: weight prep -> B fragment layout ----------------
// src [ky][kx][ic][oc] f32.  For mma.m16n8k16 B (col-major KxN):
// lane l holds halves {B[k0][n], B[k0+1][n], B[k0+8][n], B[k0+9][n]},
// k0 = (l%4)*2, n = l/4, within k-chunk ks (ic = ks*16 + k).
// dst uint2 index within tap: (ks*8 + (oc>>3))*32 + (oc&7)*4 + ((ic&7)>>1), half h = (ic&1)+((ic&8)>>2)
__global__ void __launch_bounds__(256) wprep_kernel(const float* __restrict__ c1w,
                                                    const float* __restrict__ c2w) {
    int b = blockIdx.x;            // 0..17 = conv*9 + tap
    int cw = b / 9, kk = b % 9;
    const float* src = (cw ? c2w : c1w) + kk * 4096;   // [ic][oc] slice
    __half* dst = g_wfrag + b * 4096;
#pragma unroll
    for (int i = 0; i < 16; i++) {
        int e = i * 256 + threadIdx.x;   // e = ic*64 + oc
        int ic = e >> 6, oc = e & 63;
        int ks = ic >> 4, k = ic & 15;
        int rec = (ks * 8 + (oc >> 3)) * 32 + (oc & 7) * 4 + ((k & 7) >> 1);
        int h = (k & 1) + ((k & 8) >> 2);
        dst[rec * 4 + h] = __float2half_rn(src[e]);
    }
}

// ---------------- Kernel 1: crop_and_resize -> half ----------------
__global__ void __launch_bounds__(256) crop_kernel(const float* __restrict__ feat,
                                                   const float* __restrict__ boxes,
                                                   const int* __restrict__ box_ids) {
    int blk = blockIdx.x;
    int box = blk >> 5;
    int y   = blk & 31;
    int tid = threadIdx.x;

    float by1 = boxes[box * 4 + 0];
    float bx1 = boxes[box * 4 + 1];
    float by2 = boxes[box * 4 + 2];
    float bx2 = boxes[box * 4 + 3];
    int   bi  = box_ids[box];

    float ty = (float)y * (1.0f / 31.0f);
    float ys = (by1 + ty * (by2 - by1)) * 191.0f;
    float y0f = fminf(fmaxf(floorf(ys), 0.0f), 191.0f);
    float wy = ys - y0f;
    int y0i = (int)y0f;
    int y1i = min(y0i + 1, 191);

    int x  = tid >> 3;
    int c0 = (tid & 7) * 8;
    float tx = (float)x * (1.0f / 31.0f);
    float xs = (bx1 + tx * (bx2 - bx1)) * 191.0f;
    float x0f = fminf(fmaxf(floorf(xs), 0.0f), 191.0f);
    float wx = xs - x0f;
    int x0i = (int)x0f;
    int x1i = min(x0i + 1, 191);

    const float* fb = feat + (size_t)bi * HF * WF * C;
    const float4* p00 = (const float4*)(fb + ((size_t)y0i * WF + x0i) * C + c0);
    const float4* p01 = (const float4*)(fb + ((size_t)y0i * WF + x1i) * C + c0);
    const float4* p10 = (const float4*)(fb + ((size_t)y1i * WF + x0i) * C + c0);
    const float4* p11 = (const float4*)(fb + ((size_t)y1i * WF + x1i) * C + c0);

    float omwx = 1.0f - wx, omwy = 1.0f - wy;
    __half2 hh[4];
#pragma unroll
    for (int h = 0; h < 2; h++) {
        float4 v00 = p00[h], v01 = p01[h], v10 = p10[h], v11 = p11[h];
        float4 r;
        r.x = (v00.x * omwx + v01.x * wx) * omwy + (v10.x * omwx + v11.x * wx) * wy;
        r.y = (v00.y * omwx + v01.y * wx) * omwy + (v10.y * omwx + v11.y * wx) * wy;
        r.z = (v00.z * omwx + v01.z * wx) * omwy + (v10.z * omwx + v11.z * wx) * wy;
        r.w = (v00.w * omwx + v01.w * wx) * omwy + (v10.w * omwx + v11.w * wx) * wy;
        hh[h * 2 + 0] = __floats2half2_rn(r.x, r.y);
        hh[h * 2 + 1] = __floats2half2_rn(r.z, r.w);
    }
    __half* o = g_h0 + ((size_t)(box * S + y) * S + x) * C + c0;
    *(uint4*)o = *(uint4*)hh;
}

// ---------------- Kernel 2: 3x3 SAME conv 64->64 + ReLU via mma.sync f16 ----------------
// grid (4, NBOX): blockIdx.x = 8-row tile, blockIdx.y = box. 256 threads = 8 warps.
// SMEM: halo [10 rows][34 x][64 ic] half, 16B-chunk swizzled (43520 B). No weight smem.
// Warp w: m-tile = (w&3)*64 (64 pixels), n-tile = (w>>2)*32 (32 oc). B via fragment LDG.
__global__ void __launch_bounds__(256, 2) conv_mma_kernel(const __half* __restrict__ in,
                                                          __half* __restrict__ outh,
                                                          const __half* __restrict__ wfrag,
                                                          const float* __restrict__ bias) {
    __shared__ char sm[10 * 34 * 128];
    uint32_t smb = smem_u32(sm);
    int tid = threadIdx.x;
    int box = blockIdx.y;
    int y0  = blockIdx.x * 8;

    // ---- stage halo tile (10 x 34 x 64 half, zero-padded, chunk-swizzled) ----
    {
        const char* inb = (const char*)(in + (size_t)box * 65536);
#pragma unroll
        for (int i = 0; i < 11; i++) {
            int q = i * 256 + tid;           // 16B chunk id, 0..2719
            if (q < 2720) {
                int p = q >> 3, c = q & 7;   // pixel in tile, chunk
                int r = p / 34, xs = p - r * 34;
                int gy = y0 - 1 + r, gx = xs - 1;
                uint4 v = make_uint4(0u, 0u, 0u, 0u);
                if ((unsigned)gy < 32u && (unsigned)gx < 32u)
                    v = *(const uint4*)(inb + ((size_t)(gy * 32 + gx)) * 128 + c * 16);
                *(uint4*)(sm + p * 128 + ((c ^ (p & 7)) << 4)) = v;
            }
        }
    }
    __syncthreads();

    int lane = tid & 31, w = tid >> 5;
    int mt0   = (w & 3) * 64;
    int n0    = (w >> 2) * 32;
    int nbase = (w >> 2) * 4;
    int lr    = lane & 15;
    int khalf = lane >> 4;

    int jA[4], xA[4];
#pragma unroll
    for (int mi = 0; mi < 4; mi++) {
        int m = mt0 + mi * 16 + lr;
        jA[mi] = m >> 5;
        xA[mi] = m & 31;
    }

    const uint2* wf = (const uint2*)wfrag;   // [tap][1024] uint2

    float acc[4][4][4];
#pragma unroll
    for (int mi = 0; mi < 4; mi++)
#pragma unroll
        for (int ni = 0; ni < 4; ni++)
#pragma unroll
            for (int k = 0; k < 4; k++) acc[mi][ni][k] = 0.0f;

#pragma unroll
    for (int tap = 0; tap < 9; tap++) {
        int ky = tap / 3, kx = tap - ky * 3;
        uint32_t pixb[4];
#pragma unroll
        for (int mi = 0; mi < 4; mi++)
            pixb[mi] = (jA[mi] + ky) * 34 + xA[mi] + kx;
        const uint2* wt = wf + tap * 1024;
#pragma unroll
        for (int ks = 0; ks < 4; ks++) {
            uint2 b[4];
#pragma unroll
            for (int ni = 0; ni < 4; ni++)
                b[ni] = __ldg(wt + (ks * 8 + nbase + ni) * 32 + lane);
            uint32_t kc = ks * 2 + khalf;
            uint32_t a[4][4];
#pragma unroll
            for (int mi = 0; mi < 4; mi++) {
                uint32_t ad = smb + pixb[mi] * 128 + (((kc ^ (pixb[mi] & 7)) & 7) << 4);
                ldmatrix_x4(a[mi], ad);
            }
#pragma unroll
            for (int ni = 0; ni < 4; ni++)
#pragma unroll
                for (int mi = 0; mi < 4; mi++)
                    mma16816(acc[mi][ni], a[mi], b[ni].x, b[ni].y);
        }
    }

    // ---- epilogue: bias + relu -> half ----
    int rowg = lane >> 2;
    int colg = (lane & 3) * 2;
    size_t obase = (size_t)box * 65536 + (size_t)y0 * 32 * 64;
#pragma unroll
    for (int ni = 0; ni < 4; ni++) {
        int oc = n0 + ni * 8 + colg;
        float bx = __ldg(bias + oc), by = __ldg(bias + oc + 1);
#pragma unroll
        for (int mi = 0; mi < 4; mi++) {
#pragma unroll
            for (int h = 0; h < 2; h++) {
                int m = mt0 + mi * 16 + rowg + h * 8;
                float v0 = fmaxf(acc[mi][ni][h * 2 + 0] + bx, 0.0f);
                float v1 = fmaxf(acc[mi][ni][h * 2 + 1] + by, 0.0f);
                *(__half2*)(outh + obase + (size_t)m * 64 + oc) = __floats2half2_rn(v0, v1);
            }
        }
    }
}

// ---------------- Kernel 3: 3x3 VALID conv 64->1 (selected class), half input ----------
__global__ void __launch_bounds__(256) outconv_kernel(const float* __restrict__ ow,
                                                      const float* __restrict__ obias,
                                                      const int* __restrict__ cls,
                                                      float* __restrict__ out) {
    __shared__ float sW[576];
    int box = blockIdx.x;
    int cl  = cls[box];
    int tid = threadIdx.x;
    for (int e = tid; e < 576; e += 256) sW[e] = ow[e * 3 + cl];
    __syncthreads();

    int sub = tid & 7, team = tid >> 3;
    int c0 = sub * 8;
    float4 wv[18];
#pragma unroll
    for (int p9 = 0; p9 < 9; p9++) {
        wv[p9 * 2 + 0] = *(const float4*)(sW + p9 * 64 + c0);
        wv[p9 * 2 + 1] = *(const float4*)(sW + p9 * 64 + c0 + 4);
    }
    float bb = obias[cl];
    const __half* inb = g_h0 + (size_t)box * 65536;

    for (int p = team; p < 900; p += 32) {
        int oy = p / 30;
        int ox = p - oy * 30;
        float acc = 0.0f;
#pragma unroll
        for (int ky = 0; ky < 3; ky++) {
#pragma unroll
            for (int kx = 0; kx < 3; kx++) {
                uint4 raw = *(const uint4*)(inb + ((size_t)((oy + ky) * 32 + ox + kx)) * 64 + c0);
                const __half2* hp = (const __half2*)&raw;
                int wi = (ky * 3 + kx) * 2;
                float2 f0 = __half22float2(hp[0]);
                float2 f1 = __half22float2(hp[1]);
                float2 f2 = __half22float2(hp[2]);
                float2 f3 = __half22float2(hp[3]);
                acc += f0.x * wv[wi].x + f0.y * wv[wi].y + f1.x * wv[wi].z + f1.y * wv[wi].w;
                acc += f2.x * wv[wi + 1].x + f2.y * wv[wi + 1].y + f3.x * wv[wi + 1].z + f3.y * wv[wi + 1].w;
            }
        }
        acc += __shfl_down_sync(0xffffffff, acc, 4, 8);
        acc += __shfl_down_sync(0xffffffff, acc, 2, 8);
        acc += __shfl_down_sync(0xffffffff, acc, 1, 8);
        if (sub == 0) out[(size_t)box * 900 + p] = acc + bb;
    }
}

// ---------------- launch ----------------
extern "C" void kernel_launch(void* const* d_in, const int* in_sizes, int n_in,
                              void* d_out, int out_size) {
    const float* features = (const float*)d_in[0];
    const float* boxes    = (const float*)d_in[1];
    const int*   box_ids  = (const int*)d_in[2];
    const int*   cls      = (const int*)d_in[3];
    const float* c1w      = (const float*)d_in[4];
    const float* c1b      = (const float*)d_in[5];
    const float* c2w      = (const float*)d_in[6];
    const float* c2b      = (const float*)d_in[7];
    const float* ow       = (const float*)d_in[8];
    const float* obias    = (const float*)d_in[9];
    float* out = (float*)d_out;

    __half* wf; cudaGetSymbolAddress((void**)&wf, g_wfrag);
    __half* h0; cudaGetSymbolAddress((void**)&h0, g_h0);
    __half* h1; cudaGetSymbolAddress((void**)&h1, g_h1);

    wprep_kernel<<<18, 256>>>(c1w, c2w);
    crop_kernel<<<NBOX * S, 256>>>(features, boxes, box_ids);
    conv_mma_kernel<<<dim3(4, NBOX), 256>>>(h0, h1, wf, c1b);             // conv1: h0 -> h1
    conv_mma_kernel<<<dim3(4, NBOX), 256>>>(h1, h0, wf + 9 * 4096, c2b);  // conv2: h1 -> h0
    outconv_kernel<<<NBOX, 256>>>(ow, obias, cls, out);
}